// round 12
// baseline (speedup 1.0000x reference)
#include <cuda_runtime.h>
#include <cuda_fp16.h>
#include <math.h>

#define NB 8
#define NO 128
#define NR 8
#define NH 48
#define NHW 2304
#define NX 64

// ---- output layout (concatenated flattened outputs, float32) ----
#define OFF_ATTN 0
#define OFF_Q    147456
#define OFF_PR   294912
#define OFF_A    294920
#define OFF_OFF  442376
#define OFF_TH   442384
#define OFF_Z    737296

// ---- device scratch (static, no runtime allocation) ----
// fp16 conv weights in m16n8k16 A-fragment order over row-pairs:
//   pair p: row = p / PPR, col = 2*(p % PPR) (2nd elem zero if col+1 >= K)
//   [r][wset(8)][kc][lane(32)] -> uint4 (a0,a1,a2,a3), each = half2
//   K=17: PPR=9,  NCHK=20;  K=33: PPR=17, NCHK=71
__device__ uint4 d_rh17[NR * 8 * 20 * 32];
__device__ uint4 d_rh33[NR * 8 * 71 * 32];
// fp16 conv2 weights: [branch][wset(8)][kc(8)][lane(32)] -> uint4
__device__ uint4 d_w2h[2 * 8 * 8 * 32];
__device__ float d_xout[NB * NO * NR * NHW];     // [b][c][r][hw]
__device__ float d_attn1[NB * NR * NHW];
__device__ float d_attn0[NB * 4 * NHW];
__device__ float d_z1[NB * 4 * NR * NHW];        // [b][l][r][hw]
__device__ float d_z0[NB * 4 * 4 * NHW];
__device__ float d_stats[NB * 4];                // m1, s1, m2, s2

__constant__ float c_offs[8] = {
    0.0f, 0.7853981633974483f, 1.5707963267948966f, 2.356194490192345f,
    3.141592653589793f, -2.356194490192345f, -1.5707963267948966f,
    -0.7853981633974483f};

#define LOG_SIGMA   1.1447298858494002f   // log(pi), f32
#define HALF_LOG2PI 0.9189385332046727f   // 0.5*log(2*pi), f32
#define PI_F        3.14159265358979323846f

__device__ __forceinline__ unsigned packh2(float a, float b) {
    __half2 h = __floats2half2_rn(a, b);
    return *reinterpret_cast<unsigned*>(&h);
}

#define MMA_F16(c, a0, a1, a2, a3, b0, b1)                                  \
    asm volatile(                                                           \
        "mma.sync.aligned.m16n8k16.row.col.f32.f16.f16.f32 "                \
        "{%0,%1,%2,%3}, {%4,%5,%6,%7}, {%8,%9}, {%0,%1,%2,%3};"             \
        : "+f"((c)[0]), "+f"((c)[1]), "+f"((c)[2]), "+f"((c)[3])            \
        : "r"(a0), "r"(a1), "r"(a2), "r"(a3), "r"(b0), "r"(b1))

// bilinear grid_sample (zero pad) of rotated kernel, element (i,j), chan o
template <int K>
__device__ __forceinline__ float rot_sample(const float* __restrict__ w,
                                            int r, int o, int i, int j) {
    constexpr int KK = K * K;
    float theta = 0.7853981633974483f * (float)r;
    float c = cosf(theta), s = sinf(theta);
    float gy = (2.0f * (float)i + 1.0f) / (float)K - 1.0f;
    float gx = (2.0f * (float)j + 1.0f) / (float)K - 1.0f;
    float sx = c * gx - s * gy;
    float sy = s * gx + c * gy;
    float fx = ((sx + 1.0f) * (float)K - 1.0f) * 0.5f;
    float fy = ((sy + 1.0f) * (float)K - 1.0f) * 0.5f;
    int x0 = (int)floorf(fx);
    int y0 = (int)floorf(fy);
    float wx1 = fx - (float)x0;
    float wy1 = fy - (float)y0;
    const float* wo = w + o * KK;
    auto g = [&](int y, int x) -> float {
        if (y < 0 || y >= K || x < 0 || x >= K) return 0.0f;
        return wo[y * K + x];
    };
    return g(y0, x0) * (1.0f - wy1) * (1.0f - wx1)
         + g(y0, x0 + 1) * (1.0f - wy1) * wx1
         + g(y0 + 1, x0) * wy1 * (1.0f - wx1)
         + g(y0 + 1, x0 + 1) * wy1 * wx1;
}

// ============================================================
// K1: rotate -> fp16 pair-fragment layout
//   word idx = (((r*8+wset)*NCHK+kc)*32+lane)*4+q
//   o    = 16*wset + (lane>>2) + 8*(q&1)
//   pair = kc*8 + (lane&3) + 4*(q>>1) -> (row, col=2*pc), elems col, col+1
// ============================================================
template <int K, int PPR, int NCHK>
__global__ void rotate_h(const float* __restrict__ w) {
    unsigned* out = (K == 17) ? (unsigned*)d_rh17 : (unsigned*)d_rh33;
    int idx = blockIdx.x * blockDim.x + threadIdx.x;
    if (idx >= NR * 8 * NCHK * 128) return;

    int q = idx & 3;
    int lane = (idx >> 2) & 31;
    int t = idx >> 7;
    int kc = t % NCHK; t /= NCHK;
    int wset = t & 7;
    int r = t >> 3;

    int o = 16 * wset + (lane >> 2) + 8 * (q & 1);
    int p = kc * 8 + (lane & 3) + 4 * (q >> 1);
    int row = p / PPR;
    int col = 2 * (p - row * PPR);

    float w0 = 0.0f, w1 = 0.0f;
    if (row < K) {
        w0 = rot_sample<K>(w, r, o, row, col);
        if (col + 1 < K) w1 = rot_sample<K>(w, r, o, row, col + 1);
    }
    out[idx] = packh2(w0, w1);
}

// ============================================================
// K1b: conv2 weights -> fp16 fragment order
//   o = 16*wset + (lane>>2) + 8*(q&1); c = 16*kc + 2*(lane&3) + 8*(q>>1)
// ============================================================
__global__ void w2h_frag(const float* __restrict__ w2) {
    unsigned* out = (unsigned*)d_w2h;
    int idx = blockIdx.x * blockDim.x + threadIdx.x;
    if (idx >= 2 * 8 * 8 * 128) return;
    int q = idx & 3;
    int lane = (idx >> 2) & 31;
    int t = idx >> 7;
    int kc = t % 8; t /= 8;
    int wset = t & 7;
    int br = t >> 3;
    int o = 16 * wset + (lane >> 2) + 8 * (q & 1);
    int c = 16 * kc + 2 * (lane & 3) + 8 * (q >> 1);
    const float* wb = w2 + br * 16384 + o * 128;
    out[idx] = packh2(wb[c], wb[c + 1]);
}

// ============================================================
// K2: group conv via fp16 mma.sync m16n8k16 implicit-GEMM
//   block: one (b, r), M=128 o x N=96 (2 rows x 48), 256 thr
//   warp tile: M=64 x N=24 (wm2 x wn x wj) -> each B fragment
//   feeds FOUR mma (0.5 LDS per mma); A = 4 coalesced LDG.128
//   with dist-1 prefetch. B smem offsets updated incrementally.
// ============================================================
template <int K, int PAD, int PPR, int NCHK, bool FIRST>
__global__ __launch_bounds__(256, 2) void conv_mma(
    const float* __restrict__ x, const float* __restrict__ bias,
    const float* __restrict__ kw, const float* __restrict__ gk) {
    constexpr int XCOLS = K + 49;        // fp16 columns (even)
    constexpr int XC2 = XCOLS / 2;       // 32-bit words per row
    constexpr int XROWS = K + 2;
    const uint4* rt4 = (K == 17) ? d_rh17 : d_rh33;

    __shared__ unsigned xsE[XROWS * XC2];
    __shared__ unsigned xsO[XROWS * XC2];

    int tid = threadIdx.x;
    int lane = tid & 31, wid = tid >> 5;
    int gid = lane >> 2, tig = lane & 3;
    int wm2 = wid >> 2;          // o tile: [64*wm2, 64*wm2+64)
    int wn = (wid >> 1) & 1;     // y row: y0 + wn
    int wj = wid & 1;            // n half: [24*wj, 24*wj+24)
    int y0 = blockIdx.x * 2;
    int b = blockIdx.y >> 3, r = blockIdx.y & 7;

    const float* xb = x + b * NX * NX;
    for (int idx = tid; idx < XROWS * XC2; idx += 256) {
        int row = idx / XC2, cw = idx - row * XC2;
        int gr = y0 + row - PAD;
        float v0 = 0.0f, v1 = 0.0f, v2 = 0.0f;
        if (gr >= 0 && gr < NX) {
            int gc = 2 * cw - PAD;
            if (gc >= 0 && gc < NX) v0 = xb[gr * NX + gc];
            if (gc + 1 >= 0 && gc + 1 < NX) v1 = xb[gr * NX + gc + 1];
            if (gc + 2 >= 0 && gc + 2 < NX) v2 = xb[gr * NX + gc + 2];
        }
        xsE[idx] = packh2(v0, v1);
        xsO[idx] = packh2(v1, v2);
    }
    __syncthreads();

    float acc[4][3][4];
#pragma unroll
    for (int m = 0; m < 4; ++m)
#pragma unroll
        for (int j = 0; j < 3; ++j)
#pragma unroll
            for (int e = 0; e < 4; ++e) acc[m][j][e] = 0.0f;

    const uint4* ap[4];
#pragma unroll
    for (int m = 0; m < 4; ++m)
        ap[m] = rt4 + ((size_t)(r * 8 + 4 * wm2 + m) * NCHK) * 32 + lane;

    // per-lane pair trackers: b0 pair = 8*kc + tig; b1 pair = +4
    const unsigned* cb = (gid & 1) ? xsO : xsE;
    int g2 = gid >> 1;
    int pc0 = tig, pc1 = tig + 4;
    int off0 = wn * XC2 + pc0 + g2 + wj * 12;
    int off1 = wn * XC2 + pc1 + g2 + wj * 12;

    uint4 c[4];
#pragma unroll
    for (int m = 0; m < 4; ++m) c[m] = ap[m][0];

#pragma unroll 1
    for (int kc = 0; kc < NCHK; ++kc) {
        int nx = (kc + 1 < NCHK) ? kc + 1 : kc;
        uint4 nf[4];
#pragma unroll
        for (int m = 0; m < 4; ++m) nf[m] = ap[m][(size_t)nx * 32];

        const unsigned* b0p = cb + off0;
        const unsigned* b1p = cb + off1;
        unsigned bb0[3], bb1[3];
#pragma unroll
        for (int j = 0; j < 3; ++j) {
            bb0[j] = b0p[j * 4];
            bb1[j] = b1p[j * 4];
        }
#pragma unroll
        for (int m = 0; m < 4; ++m)
#pragma unroll
            for (int j = 0; j < 3; ++j)
                MMA_F16(acc[m][j], c[m].x, c[m].y, c[m].z, c[m].w,
                        bb0[j], bb1[j]);
#pragma unroll
        for (int m = 0; m < 4; ++m) c[m] = nf[m];

        off0 += 8; pc0 += 8;
        if (pc0 >= PPR) { pc0 -= PPR; off0 += XC2 - PPR; }
        off1 += 8; pc1 += 8;
        if (pc1 >= PPR) { pc1 -= PPR; off1 += XC2 - PPR; }
    }

    // gumbel-softmax alpha over kernel sizes
    float l0 = (kw[0] + gk[0]) / 10.0f;
    float l1 = (kw[1] + gk[1]) / 10.0f;
    float mm = fmaxf(l0, l1);
    float e0 = expf(l0 - mm), e1 = expf(l1 - mm);
    float alpha = (FIRST ? e0 : e1) / (e0 + e1);

    int y = y0 + wn;
#pragma unroll
    for (int m = 0; m < 4; ++m) {
        int o_lo = 64 * wm2 + 16 * m + gid;
        int o_hi = o_lo + 8;
        float blo = bias[o_lo], bhi = bias[o_hi];
#pragma unroll
        for (int j = 0; j < 3; ++j) {
            int xc = wj * 24 + j * 8 + 2 * tig;
#pragma unroll
            for (int half = 0; half < 2; ++half) {
                int o = half ? o_hi : o_lo;
                float bb = half ? bhi : blo;
                float v0 = acc[m][j][2 * half + 0] + bb;
                float v1 = acc[m][j][2 * half + 1] + bb;
                v0 = (v0 >= 0.0f) ? v0 : 0.01f * v0;
                v1 = (v1 >= 0.0f) ? v1 : 0.01f * v1;
                v0 *= alpha;
                v1 *= alpha;
                float2* p = (float2*)(d_xout
                                      + (((b * NO + o) * NR + r) * NHW)
                                      + y * 48 + xc);
                if (FIRST) {
                    *p = make_float2(v0, v1);
                } else {
                    float2 old = *p;
                    *p = make_float2(old.x + v0, old.y + v1);
                }
            }
        }
    }
}

// ============================================================
// K3: fused conv2 + lrelu + conva/convz heads via fp16 mma
//   block: one (b, r), M=128 o x N=48, 256 thr; 8 k-chunks
//   x tile staged transposed [n][c] fp16 (stride 68 words) so B
//   pairs (c, c+1) are single aligned LDS.32, conflict-free.
// ============================================================
template <int BRANCH>
__global__ __launch_bounds__(256, 3) void gemm_mma(
    const float* __restrict__ b2, const float* __restrict__ wa,
    const float* __restrict__ ba, const float* __restrict__ wz,
    const float* __restrict__ bz) {
    constexpr int RCOUNT = BRANCH ? 8 : 4;
    constexpr int RSTEP = BRANCH ? 1 : 2;
    constexpr int STW = 68;   // words per n-row (64 + 4 pad)
    float* attn_out = BRANCH ? d_attn1 : d_attn0;
    float* z_out = BRANCH ? d_z1 : d_z0;

    __shared__ unsigned xtw[48 * STW];     // [n][c/2] fp16 pairs
    __shared__ float hbuf[4][5][48];       // per-wm4 head partials

    int tid = threadIdx.x;
    int lane = tid & 31, wid = tid >> 5;
    int gid = lane >> 2, tig = lane & 3;
    int wm4 = wid >> 1;
    int wn = wid & 1;
    int n0 = blockIdx.x * 48;
    int brs = blockIdx.y;
    int b = brs / RCOUNT;
    int rsub = brs - b * RCOUNT;
    int r = rsub * RSTEP;

    const float* xb = d_xout + ((b * NO) * NR + r) * NHW + n0;
    const int S = NR * NHW;
    for (int idx = tid; idx < 48 * 64; idx += 256) {
        int cw = idx / 48, n = idx - cw * 48;
        float v0 = xb[(2 * cw) * S + n];
        float v1 = xb[(2 * cw + 1) * S + n];
        xtw[n * STW + cw] = packh2(v0, v1);
    }
    __syncthreads();

    float acc[2][3][4];
#pragma unroll
    for (int m = 0; m < 2; ++m)
#pragma unroll
        for (int j = 0; j < 3; ++j)
#pragma unroll
            for (int e = 0; e < 4; ++e) acc[m][j][e] = 0.0f;

    const uint4* ap = d_w2h + ((BRANCH * 8 + 2 * wm4) * 8) * 32 + lane;
    const unsigned* bp = xtw + (wn * 24 + gid) * STW + tig;
#pragma unroll
    for (int kc = 0; kc < 8; ++kc) {
        uint4 A0 = ap[kc * 32];
        uint4 A1 = ap[256 + kc * 32];   // next wset (8*32)
#pragma unroll
        for (int j = 0; j < 3; ++j) {
            unsigned b0 = bp[j * 8 * STW + 8 * kc];
            unsigned b1 = bp[j * 8 * STW + 8 * kc + 4];
            MMA_F16(acc[0][j], A0.x, A0.y, A0.z, A0.w, b0, b1);
            MMA_F16(acc[1][j], A1.x, A1.y, A1.z, A1.w, b0, b1);
        }
    }

    // epilogue: h = lrelu(acc + b2[o]); head partials per lane
    float pa[3][2];
    float pz[4][3][2];
#pragma unroll
    for (int j = 0; j < 3; ++j)
#pragma unroll
        for (int c01 = 0; c01 < 2; ++c01) {
            pa[j][c01] = 0.0f;
#pragma unroll
            for (int l = 0; l < 4; ++l) pz[l][j][c01] = 0.0f;
        }

#pragma unroll
    for (int m = 0; m < 2; ++m) {
#pragma unroll
        for (int eh = 0; eh < 2; ++eh) {
            int o = 32 * wm4 + 16 * m + 8 * eh + gid;
            float bb = b2[o];
            float wav = wa[o];
            float w0 = wz[o], w1 = wz[128 + o], w2v = wz[256 + o],
                  w3 = wz[384 + o];
#pragma unroll
            for (int j = 0; j < 3; ++j) {
#pragma unroll
                for (int c01 = 0; c01 < 2; ++c01) {
                    float hv = acc[m][j][2 * eh + c01] + bb;
                    hv = (hv >= 0.0f) ? hv : 0.01f * hv;
                    pa[j][c01] = fmaf(wav, hv, pa[j][c01]);
                    pz[0][j][c01] = fmaf(w0, hv, pz[0][j][c01]);
                    pz[1][j][c01] = fmaf(w1, hv, pz[1][j][c01]);
                    pz[2][j][c01] = fmaf(w2v, hv, pz[2][j][c01]);
                    pz[3][j][c01] = fmaf(w3, hv, pz[3][j][c01]);
                }
            }
        }
    }

    // reduce over the 8 o-lane groups (lane bits 2..4)
#pragma unroll
    for (int msk = 4; msk <= 16; msk <<= 1) {
#pragma unroll
        for (int j = 0; j < 3; ++j)
#pragma unroll
            for (int c01 = 0; c01 < 2; ++c01) {
                pa[j][c01] += __shfl_xor_sync(0xffffffffu, pa[j][c01], msk);
#pragma unroll
                for (int l = 0; l < 4; ++l)
                    pz[l][j][c01] +=
                        __shfl_xor_sync(0xffffffffu, pz[l][j][c01], msk);
            }
    }

    if (lane < 4) {  // lane == tig; all gid-groups hold identical sums
#pragma unroll
        for (int j = 0; j < 3; ++j)
#pragma unroll
            for (int c01 = 0; c01 < 2; ++c01) {
                int nl = wn * 24 + j * 8 + 2 * lane + c01;
                hbuf[wm4][0][nl] = pa[j][c01];
#pragma unroll
                for (int l = 0; l < 4; ++l)
                    hbuf[wm4][1 + l][nl] = pz[l][j][c01];
            }
    }
    __syncthreads();

    for (int idx = tid; idx < 5 * 48; idx += 256) {
        int h = idx / 48, nl = idx - h * 48;
        float s = hbuf[0][h][nl] + hbuf[1][h][nl] + hbuf[2][h][nl]
                + hbuf[3][h][nl];
        int ng = n0 + nl;
        if (h == 0)
            attn_out[(b * RCOUNT + rsub) * NHW + ng] = s + ba[0];
        else
            z_out[((b * 4 + (h - 1)) * RCOUNT + rsub) * NHW + ng] =
                s + bz[h - 1];
    }
}

// ============================================================
// K4: scatter combine (betas) + p_r; writes attn, z, theta,
//     p_r, offsets directly into d_out
// ============================================================
__global__ void combine_kern(const float* __restrict__ rw,
                             const float* __restrict__ gr,
                             float* __restrict__ out) {
    int idx = blockIdx.x * blockDim.x + threadIdx.x;
    if (idx >= NB * NR * NHW) return;

    float l0 = (rw[0] + gr[0]) / 10.0f;
    float l1 = (rw[1] + gr[1]) / 10.0f;
    float mm = fmaxf(l0, l1);
    float e0 = expf(l0 - mm), e1 = expf(l1 - mm);
    float inv = 1.0f / (e0 + e1);
    float b0 = e0 * inv, b1 = e1 * inv;

    int b = idx / (NR * NHW);
    int rem = idx - b * (NR * NHW);
    int r = rem / NHW;
    int hw = rem - r * NHW;
    float off = c_offs[r];
    float t = off / PI_F;
    float pr = -0.5f * t * t - LOG_SIGMA - HALF_LOG2PI;

    float a = b1 * d_attn1[(b * NR + r) * NHW + hw];
    bool even = ((r & 1) == 0);
    if (even) a += b0 * d_attn0[(b * 4 + (r >> 1)) * NHW + hw];
    a += pr;
    out[OFF_ATTN + idx] = a;

    float zv[4];
#pragma unroll
    for (int l = 0; l < 4; ++l) {
        float z = b1 * d_z1[((b * 4 + l) * NR + r) * NHW + hw];
        if (even) z += b0 * d_z0[((b * 4 + l) * 4 + (r >> 1)) * NHW + hw];
        zv[l] = z;
        out[OFF_Z + ((b * 4 + l) * NR + r) * NHW + hw] = z;
    }
    out[OFF_TH + ((b * 2 + 0) * NR + r) * NHW + hw] = zv[0] + off;
    out[OFF_TH + ((b * 2 + 1) * NR + r) * NHW + hw] = zv[1];

    if (idx < 8) {
        float o2 = c_offs[idx];
        float t2 = o2 / PI_F;
        out[OFF_PR + idx] = -0.5f * t2 * t2 - LOG_SIGMA - HALF_LOG2PI;
        out[OFF_OFF + idx] = o2;
    }
}

// ============================================================
// K5: per-batch softmax stats (max / sumexp, two distributions)
// ============================================================
__global__ void stats_kern(const float* __restrict__ out,
                           const float* __restrict__ g) {
    __shared__ float sm[256];
    int b = blockIdx.x, tid = threadIdx.x;
    const float* a = out + OFF_ATTN + b * (NR * NHW);
    const float* gb = g + b * (NR * NHW);

    float m1 = -1e30f, m2 = -1e30f;
    for (int i = tid; i < NR * NHW; i += 256) {
        float v = a[i];
        m1 = fmaxf(m1, v);
        m2 = fmaxf(m2, v + gb[i]);
    }
    sm[tid] = m1; __syncthreads();
    for (int s = 128; s > 0; s >>= 1) {
        if (tid < s) sm[tid] = fmaxf(sm[tid], sm[tid + s]);
        __syncthreads();
    }
    m1 = sm[0]; __syncthreads();
    sm[tid] = m2; __syncthreads();
    for (int s = 128; s > 0; s >>= 1) {
        if (tid < s) sm[tid] = fmaxf(sm[tid], sm[tid + s]);
        __syncthreads();
    }
    m2 = sm[0]; __syncthreads();

    float s1 = 0.0f, s2 = 0.0f;
    for (int i = tid; i < NR * NHW; i += 256) {
        float v = a[i];
        s1 += expf(v - m1);
        s2 += expf(v + gb[i] - m2);
    }
    sm[tid] = s1; __syncthreads();
    for (int s = 128; s > 0; s >>= 1) {
        if (tid < s) sm[tid] += sm[tid + s];
        __syncthreads();
    }
    s1 = sm[0]; __syncthreads();
    sm[tid] = s2; __syncthreads();
    for (int s = 128; s > 0; s >>= 1) {
        if (tid < s) sm[tid] += sm[tid + s];
        __syncthreads();
    }
    s2 = sm[0];

    if (tid == 0) {
        d_stats[b * 4 + 0] = m1;
        d_stats[b * 4 + 1] = s1;
        d_stats[b * 4 + 2] = m2;
        d_stats[b * 4 + 3] = s2;
    }
}

// ============================================================
// K6: q_t_r (log_softmax) + a_sampled (gumbel softmax)
// ============================================================
__global__ void final_kern(const float* __restrict__ g,
                           float* __restrict__ out) {
    int idx = blockIdx.x * blockDim.x + threadIdx.x;
    if (idx >= NB * NR * NHW) return;
    int b = idx / (NR * NHW);
    float v = out[OFF_ATTN + idx];
    out[OFF_Q + idx] = (v - d_stats[b * 4 + 0]) - logf(d_stats[b * 4 + 1]);
    out[OFF_A + idx] =
        expf(v + g[idx] - d_stats[b * 4 + 2]) / d_stats[b * 4 + 3];
}

// ============================================================
extern "C" void kernel_launch(void* const* d_in, const int* in_sizes, int n_in,
                              void* d_out, int out_size) {
    const float* x   = (const float*)d_in[0];
    const float* ksw = (const float*)d_in[1];
    const float* rdw = (const float*)d_in[2];
    const float* w17 = (const float*)d_in[3];
    const float* b17 = (const float*)d_in[4];
    const float* w33 = (const float*)d_in[5];
    const float* b33 = (const float*)d_in[6];
    const float* w2  = (const float*)d_in[7];
    const float* b2  = (const float*)d_in[8];
    const float* wa  = (const float*)d_in[9];
    const float* ba  = (const float*)d_in[10];
    const float* wz  = (const float*)d_in[11];
    const float* bz  = (const float*)d_in[12];
    const float* gk  = (const float*)d_in[13];
    const float* gr  = (const float*)d_in[14];
    const float* ga  = (const float*)d_in[15];
    float* out = (float*)d_out;

    // word counts: K=17: 8*8*20*128 = 163840; K=33: 8*8*71*128 = 581632
    rotate_h<17, 9, 20><<<(163840 + 255) / 256, 256>>>(w17);
    rotate_h<33, 17, 71><<<(581632 + 255) / 256, 256>>>(w33);
    w2h_frag<<<(16384 + 255) / 256, 256>>>(w2);

    conv_mma<17, 0, 9, 20, true  ><<<dim3(24, 64), 256>>>(x, b17, ksw, gk);
    conv_mma<33, 8, 17, 71, false><<<dim3(24, 64), 256>>>(x, b33, ksw, gk);

    gemm_mma<1><<<dim3(48, 64), 256>>>(b2 + 128, wa + 128, ba + 1,
                                       wz + 512, bz + 4);
    gemm_mma<0><<<dim3(48, 32), 256>>>(b2, wa, ba, wz, bz);

    combine_kern<<<(NB * NR * NHW + 255) / 256, 256>>>(rdw, gr, out);
    stats_kern<<<NB, 256>>>(out, ga);
    final_kern<<<(NB * NR * NHW + 255) / 256, 256>>>(ga, out);
}

// round 13
// speedup vs baseline: 1.1285x; 1.1285x over previous
#include <cuda_runtime.h>
#include <cuda_fp16.h>
#include <math.h>

#define NB 8
#define NO 128
#define NR 8
#define NH 48
#define NHW 2304
#define NX 64

// ---- output layout (concatenated flattened outputs, float32) ----
#define OFF_ATTN 0
#define OFF_Q    147456
#define OFF_PR   294912
#define OFF_A    294920
#define OFF_OFF  442376
#define OFF_TH   442384
#define OFF_Z    737296

// ---- device scratch (static, no runtime allocation) ----
// fp16 conv weights in m16n8k16 A-fragment order over row-pairs:
//   pair p: row = p / PPR, col = 2*(p % PPR) (2nd elem zero if col+1 >= K)
//   [r][wset(8)][kc][lane(32)] -> uint4 (a0,a1,a2,a3), each = half2
//   K=17: PPR=9,  NCHK=20;  K=33: PPR=17, NCHK=71
__device__ uint4 d_rh17[NR * 8 * 20 * 32];
__device__ uint4 d_rh33[NR * 8 * 71 * 32];
// fp16 conv2 weights: [branch][wset(8)][kc(8)][lane(32)] -> uint4
__device__ uint4 d_w2h[2 * 8 * 8 * 32];
// conv branch outputs, fp16 channel-paired: [b][cw(64)][r][hw] half2=(c=2cw, c=2cw+1)
__device__ unsigned d_x17[NB * 64 * NR * NHW];
__device__ unsigned d_x33[NB * 64 * NR * NHW];
__device__ float d_attn1[NB * NR * NHW];
__device__ float d_attn0[NB * 4 * NHW];
__device__ float d_z1[NB * 4 * NR * NHW];        // [b][l][r][hw]
__device__ float d_z0[NB * 4 * 4 * NHW];
__device__ float d_stats[NB * 4];                // m1, s1, m2, s2

__constant__ float c_offs[8] = {
    0.0f, 0.7853981633974483f, 1.5707963267948966f, 2.356194490192345f,
    3.141592653589793f, -2.356194490192345f, -1.5707963267948966f,
    -0.7853981633974483f};

#define LOG_SIGMA   1.1447298858494002f   // log(pi), f32
#define HALF_LOG2PI 0.9189385332046727f   // 0.5*log(2*pi), f32
#define PI_F        3.14159265358979323846f

__device__ __forceinline__ unsigned packh2(float a, float b) {
    __half2 h = __floats2half2_rn(a, b);
    return *reinterpret_cast<unsigned*>(&h);
}

#define MMA_F16(c, a0, a1, a2, a3, b0, b1)                                  \
    asm volatile(                                                           \
        "mma.sync.aligned.m16n8k16.row.col.f32.f16.f16.f32 "                \
        "{%0,%1,%2,%3}, {%4,%5,%6,%7}, {%8,%9}, {%0,%1,%2,%3};"             \
        : "+f"((c)[0]), "+f"((c)[1]), "+f"((c)[2]), "+f"((c)[3])            \
        : "r"(a0), "r"(a1), "r"(a2), "r"(a3), "r"(b0), "r"(b1))

// bilinear grid_sample (zero pad) of rotated kernel, element (i,j), chan o
template <int K>
__device__ __forceinline__ float rot_sample(const float* __restrict__ w,
                                            int r, int o, int i, int j) {
    constexpr int KK = K * K;
    float theta = 0.7853981633974483f * (float)r;
    float c = cosf(theta), s = sinf(theta);
    float gy = (2.0f * (float)i + 1.0f) / (float)K - 1.0f;
    float gx = (2.0f * (float)j + 1.0f) / (float)K - 1.0f;
    float sx = c * gx - s * gy;
    float sy = s * gx + c * gy;
    float fx = ((sx + 1.0f) * (float)K - 1.0f) * 0.5f;
    float fy = ((sy + 1.0f) * (float)K - 1.0f) * 0.5f;
    int x0 = (int)floorf(fx);
    int y0 = (int)floorf(fy);
    float wx1 = fx - (float)x0;
    float wy1 = fy - (float)y0;
    const float* wo = w + o * KK;
    auto g = [&](int y, int x) -> float {
        if (y < 0 || y >= K || x < 0 || x >= K) return 0.0f;
        return wo[y * K + x];
    };
    return g(y0, x0) * (1.0f - wy1) * (1.0f - wx1)
         + g(y0, x0 + 1) * (1.0f - wy1) * wx1
         + g(y0 + 1, x0) * wy1 * (1.0f - wx1)
         + g(y0 + 1, x0 + 1) * wy1 * wx1;
}

// ============================================================
// K1: rotate -> fp16 pair-fragment layout
// ============================================================
template <int K, int PPR, int NCHK>
__global__ void rotate_h(const float* __restrict__ w) {
    unsigned* out = (K == 17) ? (unsigned*)d_rh17 : (unsigned*)d_rh33;
    int idx = blockIdx.x * blockDim.x + threadIdx.x;
    if (idx >= NR * 8 * NCHK * 128) return;

    int q = idx & 3;
    int lane = (idx >> 2) & 31;
    int t = idx >> 7;
    int kc = t % NCHK; t /= NCHK;
    int wset = t & 7;
    int r = t >> 3;

    int o = 16 * wset + (lane >> 2) + 8 * (q & 1);
    int p = kc * 8 + (lane & 3) + 4 * (q >> 1);
    int row = p / PPR;
    int col = 2 * (p - row * PPR);

    float w0 = 0.0f, w1 = 0.0f;
    if (row < K) {
        w0 = rot_sample<K>(w, r, o, row, col);
        if (col + 1 < K) w1 = rot_sample<K>(w, r, o, row, col + 1);
    }
    out[idx] = packh2(w0, w1);
}

// ============================================================
// K1b: conv2 weights -> fp16 fragment order
// ============================================================
__global__ void w2h_frag(const float* __restrict__ w2) {
    unsigned* out = (unsigned*)d_w2h;
    int idx = blockIdx.x * blockDim.x + threadIdx.x;
    if (idx >= 2 * 8 * 8 * 128) return;
    int q = idx & 3;
    int lane = (idx >> 2) & 31;
    int t = idx >> 7;
    int kc = t % 8; t /= 8;
    int wset = t & 7;
    int br = t >> 3;
    int o = 16 * wset + (lane >> 2) + 8 * (q & 1);
    int c = 16 * kc + 2 * (lane & 3) + 8 * (q >> 1);
    const float* wb = w2 + br * 16384 + o * 128;
    out[idx] = packh2(wb[c], wb[c + 1]);
}

// ============================================================
// K2: group conv via fp16 mma.sync m16n8k16 implicit-GEMM
//   (Round-10 proven tiling: warp M=32 x N=48, 8 warps, 3 blk/SM)
//   epilogue: lrelu+alpha, channel-pair via shfl_xor(4), store
//   fp16 half2 directly -> NO fp32 RMW buffer.
// ============================================================
template <int K, int PAD, int PPR, int NCHK, bool FIRST>
__global__ __launch_bounds__(256, 3) void conv_mma(
    const float* __restrict__ x, const float* __restrict__ bias,
    const float* __restrict__ kw, const float* __restrict__ gk) {
    constexpr int XCOLS = K + 49;        // fp16 columns (even)
    constexpr int XC2 = XCOLS / 2;       // 32-bit words per row
    constexpr int XROWS = K + 2;
    const uint4* rt4 = (K == 17) ? d_rh17 : d_rh33;

    __shared__ unsigned xsE[XROWS * XC2];
    __shared__ unsigned xsO[XROWS * XC2];

    int tid = threadIdx.x;
    int lane = tid & 31, wid = tid >> 5;
    int gid = lane >> 2, tig = lane & 3;
    int wm4 = wid >> 1;    // o tile: [32*wm4, 32*wm4+32)
    int wn = wid & 1;      // y row: y0 + wn
    int y0 = blockIdx.x * 2;
    int b = blockIdx.y >> 3, r = blockIdx.y & 7;

    const float* xb = x + b * NX * NX;
    for (int idx = tid; idx < XROWS * XC2; idx += 256) {
        int row = idx / XC2, cw = idx - row * XC2;
        int gr = y0 + row - PAD;
        float v0 = 0.0f, v1 = 0.0f, v2 = 0.0f;
        if (gr >= 0 && gr < NX) {
            int gc = 2 * cw - PAD;
            if (gc >= 0 && gc < NX) v0 = xb[gr * NX + gc];
            if (gc + 1 >= 0 && gc + 1 < NX) v1 = xb[gr * NX + gc + 1];
            if (gc + 2 >= 0 && gc + 2 < NX) v2 = xb[gr * NX + gc + 2];
        }
        xsE[idx] = packh2(v0, v1);
        xsO[idx] = packh2(v1, v2);
    }
    __syncthreads();

    float acc[2][6][4];
#pragma unroll
    for (int m = 0; m < 2; ++m)
#pragma unroll
        for (int j = 0; j < 6; ++j)
#pragma unroll
            for (int e = 0; e < 4; ++e) acc[m][j][e] = 0.0f;

    const uint4* ap0 =
        rt4 + ((size_t)(r * 8 + 2 * wm4) * NCHK) * 32 + lane;
    const uint4* ap1 = ap0 + (size_t)NCHK * 32;

    // per-lane pair trackers: b0 pair = 8*kc + tig; b1 pair = +4
    int row0 = 0, pc0 = tig;
    int row1 = 0, pc1 = tig + 4;
    const unsigned* cb = (gid & 1) ? xsO : xsE;
    int g2 = gid >> 1;

    uint4 c0 = ap0[0], c1 = ap1[0];

#pragma unroll 1
    for (int kc = 0; kc < NCHK; ++kc) {
        int nx = (kc + 1 < NCHK) ? kc + 1 : kc;
        uint4 n0 = ap0[(size_t)nx * 32];
        uint4 n1 = ap1[(size_t)nx * 32];

        const unsigned* b0p = cb + (wn + row0) * XC2 + pc0 + g2;
        const unsigned* b1p = cb + (wn + row1) * XC2 + pc1 + g2;
#pragma unroll
        for (int j = 0; j < 6; ++j) {
            unsigned bb0 = b0p[j * 4];
            unsigned bb1 = b1p[j * 4];
            MMA_F16(acc[0][j], c0.x, c0.y, c0.z, c0.w, bb0, bb1);
            MMA_F16(acc[1][j], c1.x, c1.y, c1.z, c1.w, bb0, bb1);
        }
        c0 = n0;
        c1 = n1;
        pc0 += 8; if (pc0 >= PPR) { pc0 -= PPR; ++row0; }
        pc1 += 8; if (pc1 >= PPR) { pc1 -= PPR; ++row1; }
    }

    // gumbel-softmax alpha over kernel sizes
    float l0 = (kw[0] + gk[0]) / 10.0f;
    float l1 = (kw[1] + gk[1]) / 10.0f;
    float mm = fmaxf(l0, l1);
    float e0 = expf(l0 - mm), e1 = expf(l1 - mm);
    float alpha = (FIRST ? e0 : e1) / (e0 + e1);

    unsigned* outb = FIRST ? d_x17 : d_x33;
    int y = y0 + wn;
    bool evenG = ((gid & 1) == 0);
    int g2o = gid >> 1;
#pragma unroll
    for (int m = 0; m < 2; ++m) {
        int o_lo = 32 * wm4 + 16 * m + gid;
        int o_hi = o_lo + 8;
        float blo = bias[o_lo], bhi = bias[o_hi];
#pragma unroll
        for (int j = 0; j < 6; ++j) {
            int xc = j * 8 + 2 * tig;
#pragma unroll
            for (int half = 0; half < 2; ++half) {
                float bb = half ? bhi : blo;
                float v0 = acc[m][j][2 * half + 0] + bb;
                float v1 = acc[m][j][2 * half + 1] + bb;
                v0 = (v0 >= 0.0f) ? v0 : 0.01f * v0;
                v1 = (v1 >= 0.0f) ? v1 : 0.01f * v1;
                v0 *= alpha;
                v1 *= alpha;
                unsigned h = packh2(v0, v1);
                unsigned ph = __shfl_xor_sync(0xffffffffu, h, 4);
                if (evenG) {
                    // word at hw=xc:   (c=2cw, c=2cw+1) = (h.lo, ph.lo)
                    // word at hw=xc+1: (h.hi, ph.hi)
                    unsigned w0 = (h & 0xffffu) | (ph << 16);
                    unsigned w1 = (h >> 16) | (ph & 0xffff0000u);
                    int cw = 16 * wm4 + 8 * m + g2o + 4 * half;
                    size_t base = ((size_t)(b * 64 + cw) * 8 + r) * NHW
                                  + y * 48 + xc;
                    *(uint2*)(outb + base) = make_uint2(w0, w1);
                }
            }
        }
    }
}

// ============================================================
// K3: fused conv2 + lrelu + conva/convz heads via fp16 mma
//   staging: xt = hadd2(x17, x33) -- half2 IS the mma k-pair.
// ============================================================
template <int BRANCH>
__global__ __launch_bounds__(256, 3) void gemm_mma(
    const float* __restrict__ b2, const float* __restrict__ wa,
    const float* __restrict__ ba, const float* __restrict__ wz,
    const float* __restrict__ bz) {
    constexpr int RCOUNT = BRANCH ? 8 : 4;
    constexpr int RSTEP = BRANCH ? 1 : 2;
    constexpr int STW = 68;   // words per n-row (64 + 4 pad)
    float* attn_out = BRANCH ? d_attn1 : d_attn0;
    float* z_out = BRANCH ? d_z1 : d_z0;

    __shared__ unsigned xtw[48 * STW];     // [n][c/2] fp16 pairs
    __shared__ float hbuf[4][5][48];       // per-wm4 head partials

    int tid = threadIdx.x;
    int lane = tid & 31, wid = tid >> 5;
    int gid = lane >> 2, tig = lane & 3;
    int wm4 = wid >> 1;
    int wn = wid & 1;
    int n0 = blockIdx.x * 48;
    int brs = blockIdx.y;
    int b = brs / RCOUNT;
    int rsub = brs - b * RCOUNT;
    int r = rsub * RSTEP;

    size_t p0 = ((size_t)(b * 512 + r)) * NHW + n0;
    for (int idx = tid; idx < 64 * 48; idx += 256) {
        int cw = idx / 48, n = idx - cw * 48;
        size_t off = p0 + (size_t)cw * (8 * NHW) + n;
        __half2 va = *(const __half2*)(d_x17 + off);
        __half2 vb = *(const __half2*)(d_x33 + off);
        __half2 s = __hadd2(va, vb);
        xtw[n * STW + cw] = *reinterpret_cast<unsigned*>(&s);
    }
    __syncthreads();

    float acc[2][3][4];
#pragma unroll
    for (int m = 0; m < 2; ++m)
#pragma unroll
        for (int j = 0; j < 3; ++j)
#pragma unroll
            for (int e = 0; e < 4; ++e) acc[m][j][e] = 0.0f;

    const uint4* ap = d_w2h + ((BRANCH * 8 + 2 * wm4) * 8) * 32 + lane;
    const unsigned* bp = xtw + (wn * 24 + gid) * STW + tig;
#pragma unroll
    for (int kc = 0; kc < 8; ++kc) {
        uint4 A0 = ap[kc * 32];
        uint4 A1 = ap[256 + kc * 32];   // next wset (8*32)
#pragma unroll
        for (int j = 0; j < 3; ++j) {
            unsigned b0 = bp[j * 8 * STW + 8 * kc];
            unsigned b1 = bp[j * 8 * STW + 8 * kc + 4];
            MMA_F16(acc[0][j], A0.x, A0.y, A0.z, A0.w, b0, b1);
            MMA_F16(acc[1][j], A1.x, A1.y, A1.z, A1.w, b0, b1);
        }
    }

    // epilogue: h = lrelu(acc + b2[o]); head partials per lane
    float pa[3][2];
    float pz[4][3][2];
#pragma unroll
    for (int j = 0; j < 3; ++j)
#pragma unroll
        for (int c01 = 0; c01 < 2; ++c01) {
            pa[j][c01] = 0.0f;
#pragma unroll
            for (int l = 0; l < 4; ++l) pz[l][j][c01] = 0.0f;
        }

#pragma unroll
    for (int m = 0; m < 2; ++m) {
#pragma unroll
        for (int eh = 0; eh < 2; ++eh) {
            int o = 32 * wm4 + 16 * m + 8 * eh + gid;
            float bb = b2[o];
            float wav = wa[o];
            float w0 = wz[o], w1 = wz[128 + o], w2v = wz[256 + o],
                  w3 = wz[384 + o];
#pragma unroll
            for (int j = 0; j < 3; ++j) {
#pragma unroll
                for (int c01 = 0; c01 < 2; ++c01) {
                    float hv = acc[m][j][2 * eh + c01] + bb;
                    hv = (hv >= 0.0f) ? hv : 0.01f * hv;
                    pa[j][c01] = fmaf(wav, hv, pa[j][c01]);
                    pz[0][j][c01] = fmaf(w0, hv, pz[0][j][c01]);
                    pz[1][j][c01] = fmaf(w1, hv, pz[1][j][c01]);
                    pz[2][j][c01] = fmaf(w2v, hv, pz[2][j][c01]);
                    pz[3][j][c01] = fmaf(w3, hv, pz[3][j][c01]);
                }
            }
        }
    }

    // reduce over the 8 o-lane groups (lane bits 2..4)
#pragma unroll
    for (int msk = 4; msk <= 16; msk <<= 1) {
#pragma unroll
        for (int j = 0; j < 3; ++j)
#pragma unroll
            for (int c01 = 0; c01 < 2; ++c01) {
                pa[j][c01] += __shfl_xor_sync(0xffffffffu, pa[j][c01], msk);
#pragma unroll
                for (int l = 0; l < 4; ++l)
                    pz[l][j][c01] +=
                        __shfl_xor_sync(0xffffffffu, pz[l][j][c01], msk);
            }
    }

    if (lane < 4) {  // lane == tig; all gid-groups hold identical sums
#pragma unroll
        for (int j = 0; j < 3; ++j)
#pragma unroll
            for (int c01 = 0; c01 < 2; ++c01) {
                int nl = wn * 24 + j * 8 + 2 * lane + c01;
                hbuf[wm4][0][nl] = pa[j][c01];
#pragma unroll
                for (int l = 0; l < 4; ++l)
                    hbuf[wm4][1 + l][nl] = pz[l][j][c01];
            }
    }
    __syncthreads();

    for (int idx = tid; idx < 5 * 48; idx += 256) {
        int h = idx / 48, nl = idx - h * 48;
        float s = hbuf[0][h][nl] + hbuf[1][h][nl] + hbuf[2][h][nl]
                + hbuf[3][h][nl];
        int ng = n0 + nl;
        if (h == 0)
            attn_out[(b * RCOUNT + rsub) * NHW + ng] = s + ba[0];
        else
            z_out[((b * 4 + (h - 1)) * RCOUNT + rsub) * NHW + ng] =
                s + bz[h - 1];
    }
}

// ============================================================
// K4: scatter combine (betas) + p_r; writes attn, z, theta,
//     p_r, offsets directly into d_out
// ============================================================
__global__ void combine_kern(const float* __restrict__ rw,
                             const float* __restrict__ gr,
                             float* __restrict__ out) {
    int idx = blockIdx.x * blockDim.x + threadIdx.x;
    if (idx >= NB * NR * NHW) return;

    float l0 = (rw[0] + gr[0]) / 10.0f;
    float l1 = (rw[1] + gr[1]) / 10.0f;
    float mm = fmaxf(l0, l1);
    float e0 = expf(l0 - mm), e1 = expf(l1 - mm);
    float inv = 1.0f / (e0 + e1);
    float b0 = e0 * inv, b1 = e1 * inv;

    int b = idx / (NR * NHW);
    int rem = idx - b * (NR * NHW);
    int r = rem / NHW;
    int hw = rem - r * NHW;
    float off = c_offs[r];
    float t = off / PI_F;
    float pr = -0.5f * t * t - LOG_SIGMA - HALF_LOG2PI;

    float a = b1 * d_attn1[(b * NR + r) * NHW + hw];
    bool even = ((r & 1) == 0);
    if (even) a += b0 * d_attn0[(b * 4 + (r >> 1)) * NHW + hw];
    a += pr;
    out[OFF_ATTN + idx] = a;

    float zv[4];
#pragma unroll
    for (int l = 0; l < 4; ++l) {
        float z = b1 * d_z1[((b * 4 + l) * NR + r) * NHW + hw];
        if (even) z += b0 * d_z0[((b * 4 + l) * 4 + (r >> 1)) * NHW + hw];
        zv[l] = z;
        out[OFF_Z + ((b * 4 + l) * NR + r) * NHW + hw] = z;
    }
    out[OFF_TH + ((b * 2 + 0) * NR + r) * NHW + hw] = zv[0] + off;
    out[OFF_TH + ((b * 2 + 1) * NR + r) * NHW + hw] = zv[1];

    if (idx < 8) {
        float o2 = c_offs[idx];
        float t2 = o2 / PI_F;
        out[OFF_PR + idx] = -0.5f * t2 * t2 - LOG_SIGMA - HALF_LOG2PI;
        out[OFF_OFF + idx] = o2;
    }
}

// ============================================================
// K5: per-batch softmax stats (max / sumexp, two distributions)
// ============================================================
__global__ void stats_kern(const float* __restrict__ out,
                           const float* __restrict__ g) {
    __shared__ float sm[256];
    int b = blockIdx.x, tid = threadIdx.x;
    const float* a = out + OFF_ATTN + b * (NR * NHW);
    const float* gb = g + b * (NR * NHW);

    float m1 = -1e30f, m2 = -1e30f;
    for (int i = tid; i < NR * NHW; i += 256) {
        float v = a[i];
        m1 = fmaxf(m1, v);
        m2 = fmaxf(m2, v + gb[i]);
    }
    sm[tid] = m1; __syncthreads();
    for (int s = 128; s > 0; s >>= 1) {
        if (tid < s) sm[tid] = fmaxf(sm[tid], sm[tid + s]);
        __syncthreads();
    }
    m1 = sm[0]; __syncthreads();
    sm[tid] = m2; __syncthreads();
    for (int s = 128; s > 0; s >>= 1) {
        if (tid < s) sm[tid] = fmaxf(sm[tid], sm[tid + s]);
        __syncthreads();
    }
    m2 = sm[0]; __syncthreads();

    float s1 = 0.0f, s2 = 0.0f;
    for (int i = tid; i < NR * NHW; i += 256) {
        float v = a[i];
        s1 += expf(v - m1);
        s2 += expf(v + gb[i] - m2);
    }
    sm[tid] = s1; __syncthreads();
    for (int s = 128; s > 0; s >>= 1) {
        if (tid < s) sm[tid] += sm[tid + s];
        __syncthreads();
    }
    s1 = sm[0]; __syncthreads();
    sm[tid] = s2; __syncthreads();
    for (int s = 128; s > 0; s >>= 1) {
        if (tid < s) sm[tid] += sm[tid + s];
        __syncthreads();
    }
    s2 = sm[0];

    if (tid == 0) {
        d_stats[b * 4 + 0] = m1;
        d_stats[b * 4 + 1] = s1;
        d_stats[b * 4 + 2] = m2;
        d_stats[b * 4 + 3] = s2;
    }
}

// ============================================================
// K6: q_t_r (log_softmax) + a_sampled (gumbel softmax)
// ============================================================
__global__ void final_kern(const float* __restrict__ g,
                           float* __restrict__ out) {
    int idx = blockIdx.x * blockDim.x + threadIdx.x;
    if (idx >= NB * NR * NHW) return;
    int b = idx / (NR * NHW);
    float v = out[OFF_ATTN + idx];
    out[OFF_Q + idx] = (v - d_stats[b * 4 + 0]) - logf(d_stats[b * 4 + 1]);
    out[OFF_A + idx] =
        expf(v + g[idx] - d_stats[b * 4 + 2]) / d_stats[b * 4 + 3];
}

// ============================================================
extern "C" void kernel_launch(void* const* d_in, const int* in_sizes, int n_in,
                              void* d_out, int out_size) {
    const float* x   = (const float*)d_in[0];
    const float* ksw = (const float*)d_in[1];
    const float* rdw = (const float*)d_in[2];
    const float* w17 = (const float*)d_in[3];
    const float* b17 = (const float*)d_in[4];
    const float* w33 = (const float*)d_in[5];
    const float* b33 = (const float*)d_in[6];
    const float* w2  = (const float*)d_in[7];
    const float* b2  = (const float*)d_in[8];
    const float* wa  = (const float*)d_in[9];
    const float* ba  = (const float*)d_in[10];
    const float* wz  = (const float*)d_in[11];
    const float* bz  = (const float*)d_in[12];
    const float* gk  = (const float*)d_in[13];
    const float* gr  = (const float*)d_in[14];
    const float* ga  = (const float*)d_in[15];
    float* out = (float*)d_out;

    // word counts: K=17: 8*8*20*128 = 163840; K=33: 8*8*71*128 = 581632
    rotate_h<17, 9, 20><<<(163840 + 255) / 256, 256>>>(w17);
    rotate_h<33, 17, 71><<<(581632 + 255) / 256, 256>>>(w33);
    w2h_frag<<<(16384 + 255) / 256, 256>>>(w2);

    conv_mma<17, 0, 9, 20, true  ><<<dim3(24, 64), 256>>>(x, b17, ksw, gk);
    conv_mma<33, 8, 17, 71, false><<<dim3(24, 64), 256>>>(x, b33, ksw, gk);

    gemm_mma<1><<<dim3(48, 64), 256>>>(b2 + 128, wa + 128, ba + 1,
                                       wz + 512, bz + 4);
    gemm_mma<0><<<dim3(48, 32), 256>>>(b2, wa, ba, wz, bz);

    combine_kern<<<(NB * NR * NHW + 255) / 256, 256>>>(rdw, gr, out);
    stats_kern<<<NB, 256>>>(out, ga);
    final_kern<<<(NB * NR * NHW + 255) / 256, 256>>>(ga, out);
}

// round 14
// speedup vs baseline: 1.2341x; 1.0936x over previous
#include <cuda_runtime.h>
#include <cuda_fp16.h>
#include <math.h>

#define NB 8
#define NO 128
#define NR 8
#define NH 48
#define NHW 2304
#define NX 64

// ---- output layout (concatenated flattened outputs, float32) ----
#define OFF_ATTN 0
#define OFF_Q    147456
#define OFF_PR   294912
#define OFF_A    294920
#define OFF_OFF  442376
#define OFF_TH   442384
#define OFF_Z    737296

// ---- device scratch (static, no runtime allocation) ----
// fp16 conv weights in m16n8k16 A-fragment order over row-pairs:
//   pair p: row = p / PPR, col = 2*(p % PPR) (2nd elem zero if col+1 >= K)
//   [r][wset(8)][kc][lane(32)] -> uint4 (a0,a1,a2,a3), each = half2
//   K=17: PPR=9,  NCHK=20;  K=33: PPR=17, NCHK=71
__device__ uint4 d_rh17[NR * 8 * 20 * 32];
__device__ uint4 d_rh33[NR * 8 * 71 * 32];
// fp16 conv2 weights: [branch][wset(8)][kc(8)][lane(32)] -> uint4
__device__ uint4 d_w2h[2 * 8 * 8 * 32];
// conv branch outputs, fp16 channel-paired: [b][cw(64)][r][hw] half2=(c=2cw, c=2cw+1)
__device__ unsigned d_x17[NB * 64 * NR * NHW];
__device__ unsigned d_x33[NB * 64 * NR * NHW];
__device__ float d_attn1[NB * NR * NHW];
__device__ float d_attn0[NB * 4 * NHW];
__device__ float d_z1[NB * 4 * NR * NHW];        // [b][l][r][hw]
__device__ float d_z0[NB * 4 * 4 * NHW];
__device__ float d_stats[NB * 4];                // m1, s1, m2, s2

__constant__ float c_offs[8] = {
    0.0f, 0.7853981633974483f, 1.5707963267948966f, 2.356194490192345f,
    3.141592653589793f, -2.356194490192345f, -1.5707963267948966f,
    -0.7853981633974483f};

#define LOG_SIGMA   1.1447298858494002f   // log(pi), f32
#define HALF_LOG2PI 0.9189385332046727f   // 0.5*log(2*pi), f32
#define PI_F        3.14159265358979323846f

__device__ __forceinline__ unsigned packh2(float a, float b) {
    __half2 h = __floats2half2_rn(a, b);
    return *reinterpret_cast<unsigned*>(&h);
}

#define MMA_F16(c, a0, a1, a2, a3, b0, b1)                                  \
    asm volatile(                                                           \
        "mma.sync.aligned.m16n8k16.row.col.f32.f16.f16.f32 "                \
        "{%0,%1,%2,%3}, {%4,%5,%6,%7}, {%8,%9}, {%0,%1,%2,%3};"             \
        : "+f"((c)[0]), "+f"((c)[1]), "+f"((c)[2]), "+f"((c)[3])            \
        : "r"(a0), "r"(a1), "r"(a2), "r"(a3), "r"(b0), "r"(b1))

// bilinear grid_sample (zero pad) of rotated kernel, element (i,j), chan o
template <int K>
__device__ __forceinline__ float rot_sample(const float* __restrict__ w,
                                            int r, int o, int i, int j) {
    constexpr int KK = K * K;
    float theta = 0.7853981633974483f * (float)r;
    float c = cosf(theta), s = sinf(theta);
    float gy = (2.0f * (float)i + 1.0f) / (float)K - 1.0f;
    float gx = (2.0f * (float)j + 1.0f) / (float)K - 1.0f;
    float sx = c * gx - s * gy;
    float sy = s * gx + c * gy;
    float fx = ((sx + 1.0f) * (float)K - 1.0f) * 0.5f;
    float fy = ((sy + 1.0f) * (float)K - 1.0f) * 0.5f;
    int x0 = (int)floorf(fx);
    int y0 = (int)floorf(fy);
    float wx1 = fx - (float)x0;
    float wy1 = fy - (float)y0;
    const float* wo = w + o * KK;
    auto g = [&](int y, int x) -> float {
        if (y < 0 || y >= K || x < 0 || x >= K) return 0.0f;
        return wo[y * K + x];
    };
    return g(y0, x0) * (1.0f - wy1) * (1.0f - wx1)
         + g(y0, x0 + 1) * (1.0f - wy1) * wx1
         + g(y0 + 1, x0) * wy1 * (1.0f - wx1)
         + g(y0 + 1, x0 + 1) * wy1 * wx1;
}

// ============================================================
// K1: rotate -> fp16 pair-fragment layout
// ============================================================
template <int K, int PPR, int NCHK>
__global__ void rotate_h(const float* __restrict__ w) {
    unsigned* out = (K == 17) ? (unsigned*)d_rh17 : (unsigned*)d_rh33;
    int idx = blockIdx.x * blockDim.x + threadIdx.x;
    if (idx >= NR * 8 * NCHK * 128) return;

    int q = idx & 3;
    int lane = (idx >> 2) & 31;
    int t = idx >> 7;
    int kc = t % NCHK; t /= NCHK;
    int wset = t & 7;
    int r = t >> 3;

    int o = 16 * wset + (lane >> 2) + 8 * (q & 1);
    int p = kc * 8 + (lane & 3) + 4 * (q >> 1);
    int row = p / PPR;
    int col = 2 * (p - row * PPR);

    float w0 = 0.0f, w1 = 0.0f;
    if (row < K) {
        w0 = rot_sample<K>(w, r, o, row, col);
        if (col + 1 < K) w1 = rot_sample<K>(w, r, o, row, col + 1);
    }
    out[idx] = packh2(w0, w1);
}

// ============================================================
// K1b: conv2 weights -> fp16 fragment order
// ============================================================
__global__ void w2h_frag(const float* __restrict__ w2) {
    unsigned* out = (unsigned*)d_w2h;
    int idx = blockIdx.x * blockDim.x + threadIdx.x;
    if (idx >= 2 * 8 * 8 * 128) return;
    int q = idx & 3;
    int lane = (idx >> 2) & 31;
    int t = idx >> 7;
    int kc = t % 8; t /= 8;
    int wset = t & 7;
    int br = t >> 3;
    int o = 16 * wset + (lane >> 2) + 8 * (q & 1);
    int c = 16 * kc + 2 * (lane & 3) + 8 * (q >> 1);
    const float* wb = w2 + br * 16384 + o * 128;
    out[idx] = packh2(wb[c], wb[c + 1]);
}

// ============================================================
// K2 body: group conv via fp16 mma.sync m16n8k16 implicit-GEMM
//   warp M=32 x N=48, 8 warps; incremental B offsets; fp16
//   channel-paired direct store (no RMW).
// ============================================================
template <int K, int PAD, int PPR, int NCHK, bool FIRST>
__device__ __forceinline__ void conv_body(
    unsigned* xsE, unsigned* xsO,
    const float* __restrict__ x, const float* __restrict__ bias,
    const float* __restrict__ kw, const float* __restrict__ gk, int by) {
    constexpr int XCOLS = K + 49;        // fp16 columns (even)
    constexpr int XC2 = XCOLS / 2;       // 32-bit words per row
    constexpr int XROWS = K + 2;
    const uint4* rt4 = (K == 17) ? d_rh17 : d_rh33;

    int tid = threadIdx.x;
    int lane = tid & 31, wid = tid >> 5;
    int gid = lane >> 2, tig = lane & 3;
    int wm4 = wid >> 1;    // o tile: [32*wm4, 32*wm4+32)
    int wn = wid & 1;      // y row: y0 + wn
    int y0 = blockIdx.x * 2;
    int b = by >> 3, r = by & 7;

    const float* xb = x + b * NX * NX;
    for (int idx = tid; idx < XROWS * XC2; idx += 256) {
        int row = idx / XC2, cw = idx - row * XC2;
        int gr = y0 + row - PAD;
        float v0 = 0.0f, v1 = 0.0f, v2 = 0.0f;
        if (gr >= 0 && gr < NX) {
            int gc = 2 * cw - PAD;
            if (gc >= 0 && gc < NX) v0 = xb[gr * NX + gc];
            if (gc + 1 >= 0 && gc + 1 < NX) v1 = xb[gr * NX + gc + 1];
            if (gc + 2 >= 0 && gc + 2 < NX) v2 = xb[gr * NX + gc + 2];
        }
        xsE[idx] = packh2(v0, v1);
        xsO[idx] = packh2(v1, v2);
    }
    __syncthreads();

    float acc[2][6][4];
#pragma unroll
    for (int m = 0; m < 2; ++m)
#pragma unroll
        for (int j = 0; j < 6; ++j)
#pragma unroll
            for (int e = 0; e < 4; ++e) acc[m][j][e] = 0.0f;

    const uint4* ap0 =
        rt4 + ((size_t)(r * 8 + 2 * wm4) * NCHK) * 32 + lane;
    const uint4* ap1 = ap0 + (size_t)NCHK * 32;

    // per-lane pair trackers with incremental smem offsets
    const unsigned* cb = (gid & 1) ? xsO : xsE;
    int g2 = gid >> 1;
    int pc0 = tig, pc1 = tig + 4;
    int off0 = wn * XC2 + pc0 + g2;
    int off1 = wn * XC2 + pc1 + g2;

    uint4 c0 = ap0[0], c1 = ap1[0];

#pragma unroll 1
    for (int kc = 0; kc < NCHK; ++kc) {
        int nx = (kc + 1 < NCHK) ? kc + 1 : kc;
        uint4 n0 = ap0[(size_t)nx * 32];
        uint4 n1 = ap1[(size_t)nx * 32];

        const unsigned* b0p = cb + off0;
        const unsigned* b1p = cb + off1;
#pragma unroll
        for (int j = 0; j < 6; ++j) {
            unsigned bb0 = b0p[j * 4];
            unsigned bb1 = b1p[j * 4];
            MMA_F16(acc[0][j], c0.x, c0.y, c0.z, c0.w, bb0, bb1);
            MMA_F16(acc[1][j], c1.x, c1.y, c1.z, c1.w, bb0, bb1);
        }
        c0 = n0;
        c1 = n1;
        off0 += 8; pc0 += 8;
        if (pc0 >= PPR) { pc0 -= PPR; off0 += XC2 - PPR; }
        off1 += 8; pc1 += 8;
        if (pc1 >= PPR) { pc1 -= PPR; off1 += XC2 - PPR; }
    }

    // gumbel-softmax alpha over kernel sizes
    float l0 = (kw[0] + gk[0]) / 10.0f;
    float l1 = (kw[1] + gk[1]) / 10.0f;
    float mm = fmaxf(l0, l1);
    float e0 = expf(l0 - mm), e1 = expf(l1 - mm);
    float alpha = (FIRST ? e0 : e1) / (e0 + e1);

    unsigned* outb = FIRST ? d_x17 : d_x33;
    int y = y0 + wn;
    bool evenG = ((gid & 1) == 0);
    int g2o = gid >> 1;
#pragma unroll
    for (int m = 0; m < 2; ++m) {
        int o_lo = 32 * wm4 + 16 * m + gid;
        int o_hi = o_lo + 8;
        float blo = bias[o_lo], bhi = bias[o_hi];
#pragma unroll
        for (int j = 0; j < 6; ++j) {
            int xc = j * 8 + 2 * tig;
#pragma unroll
            for (int half = 0; half < 2; ++half) {
                float bb = half ? bhi : blo;
                float v0 = acc[m][j][2 * half + 0] + bb;
                float v1 = acc[m][j][2 * half + 1] + bb;
                v0 = (v0 >= 0.0f) ? v0 : 0.01f * v0;
                v1 = (v1 >= 0.0f) ? v1 : 0.01f * v1;
                v0 *= alpha;
                v1 *= alpha;
                unsigned h = packh2(v0, v1);
                unsigned ph = __shfl_xor_sync(0xffffffffu, h, 4);
                if (evenG) {
                    unsigned w0 = (h & 0xffffu) | (ph << 16);
                    unsigned w1 = (h >> 16) | (ph & 0xffff0000u);
                    int cw = 16 * wm4 + 8 * m + g2o + 4 * half;
                    size_t base = ((size_t)(b * 64 + cw) * 8 + r) * NHW
                                  + y * 48 + xc;
                    *(uint2*)(outb + base) = make_uint2(w0, w1);
                }
            }
        }
    }
}

// fused conv launch: grid.y in [0,128): y<64 -> K17, else K33.
// K17 blocks are scheduled first; K33 blocks backfill their tail.
__global__ __launch_bounds__(256, 3) void conv_fused(
    const float* __restrict__ x,
    const float* __restrict__ b17, const float* __restrict__ b33,
    const float* __restrict__ kw, const float* __restrict__ gk) {
    // sized for K=33 config: XROWS=35, XC2=41
    __shared__ unsigned xsE[35 * 41];
    __shared__ unsigned xsO[35 * 41];
    if (blockIdx.y < 64)
        conv_body<17, 0, 9, 20, true>(xsE, xsO, x, b17, kw, gk,
                                      blockIdx.y);
    else
        conv_body<33, 8, 17, 71, false>(xsE, xsO, x, b33, kw, gk,
                                        blockIdx.y - 64);
}

// ============================================================
// K3: fused conv2 + lrelu + conva/convz heads via fp16 mma
//   ONE launch: every (b,r) block stages xt = hadd2(x17,x33)
//   once; pass 0 = branch 1 (all r), pass 1 = branch 0 (even r).
// ============================================================
__global__ __launch_bounds__(256, 3) void gemm_fused(
    const float* __restrict__ b2, const float* __restrict__ wa,
    const float* __restrict__ ba, const float* __restrict__ wz,
    const float* __restrict__ bz) {
    constexpr int STW = 68;   // words per n-row (64 + 4 pad)

    __shared__ unsigned xtw[48 * STW];     // [n][c/2] fp16 pairs
    __shared__ float hbuf[4][5][48];       // per-wm4 head partials

    int tid = threadIdx.x;
    int lane = tid & 31, wid = tid >> 5;
    int gid = lane >> 2, tig = lane & 3;
    int wm4 = wid >> 1;
    int wn = wid & 1;
    int n0 = blockIdx.x * 48;
    int brs = blockIdx.y;
    int b = brs >> 3;
    int r = brs & 7;

    size_t p0 = ((size_t)(b * 512 + r)) * NHW + n0;
    for (int idx = tid; idx < 64 * 48; idx += 256) {
        int cw = idx / 48, n = idx - cw * 48;
        size_t off = p0 + (size_t)cw * (8 * NHW) + n;
        __half2 va = *(const __half2*)(d_x17 + off);
        __half2 vb = *(const __half2*)(d_x33 + off);
        __half2 s = __hadd2(va, vb);
        xtw[n * STW + cw] = *reinterpret_cast<unsigned*>(&s);
    }
    __syncthreads();

    int passes = ((r & 1) == 0) ? 2 : 1;
#pragma unroll 1
    for (int pass = 0; pass < passes; ++pass) {
        int BR = (pass == 0) ? 1 : 0;
        const float* b2p = b2 + BR * 128;
        const float* wap = wa + BR * 128;
        const float* bap = ba + BR;
        const float* wzp = wz + BR * 512;
        const float* bzp = bz + BR * 4;
        float* attn_out = BR ? d_attn1 : d_attn0;
        float* z_out = BR ? d_z1 : d_z0;
        int RCOUNT = BR ? 8 : 4;
        int rsub = BR ? r : (r >> 1);

        float acc[2][3][4];
#pragma unroll
        for (int m = 0; m < 2; ++m)
#pragma unroll
            for (int j = 0; j < 3; ++j)
#pragma unroll
                for (int e = 0; e < 4; ++e) acc[m][j][e] = 0.0f;

        const uint4* ap = d_w2h + ((BR * 8 + 2 * wm4) * 8) * 32 + lane;
        const unsigned* bp = xtw + (wn * 24 + gid) * STW + tig;
#pragma unroll
        for (int kc = 0; kc < 8; ++kc) {
            uint4 A0 = ap[kc * 32];
            uint4 A1 = ap[256 + kc * 32];   // next wset (8*32)
#pragma unroll
            for (int j = 0; j < 3; ++j) {
                unsigned bb0 = bp[j * 8 * STW + 8 * kc];
                unsigned bb1 = bp[j * 8 * STW + 8 * kc + 4];
                MMA_F16(acc[0][j], A0.x, A0.y, A0.z, A0.w, bb0, bb1);
                MMA_F16(acc[1][j], A1.x, A1.y, A1.z, A1.w, bb0, bb1);
            }
        }

        // epilogue: h = lrelu(acc + b2[o]); head partials per lane
        float pa[3][2];
        float pz[4][3][2];
#pragma unroll
        for (int j = 0; j < 3; ++j)
#pragma unroll
            for (int c01 = 0; c01 < 2; ++c01) {
                pa[j][c01] = 0.0f;
#pragma unroll
                for (int l = 0; l < 4; ++l) pz[l][j][c01] = 0.0f;
            }

#pragma unroll
        for (int m = 0; m < 2; ++m) {
#pragma unroll
            for (int eh = 0; eh < 2; ++eh) {
                int o = 32 * wm4 + 16 * m + 8 * eh + gid;
                float bb = b2p[o];
                float wav = wap[o];
                float w0 = wzp[o], w1 = wzp[128 + o], w2v = wzp[256 + o],
                      w3 = wzp[384 + o];
#pragma unroll
                for (int j = 0; j < 3; ++j) {
#pragma unroll
                    for (int c01 = 0; c01 < 2; ++c01) {
                        float hv = acc[m][j][2 * eh + c01] + bb;
                        hv = (hv >= 0.0f) ? hv : 0.01f * hv;
                        pa[j][c01] = fmaf(wav, hv, pa[j][c01]);
                        pz[0][j][c01] = fmaf(w0, hv, pz[0][j][c01]);
                        pz[1][j][c01] = fmaf(w1, hv, pz[1][j][c01]);
                        pz[2][j][c01] = fmaf(w2v, hv, pz[2][j][c01]);
                        pz[3][j][c01] = fmaf(w3, hv, pz[3][j][c01]);
                    }
                }
            }
        }

        // reduce over the 8 o-lane groups (lane bits 2..4)
#pragma unroll
        for (int msk = 4; msk <= 16; msk <<= 1) {
#pragma unroll
            for (int j = 0; j < 3; ++j)
#pragma unroll
                for (int c01 = 0; c01 < 2; ++c01) {
                    pa[j][c01] +=
                        __shfl_xor_sync(0xffffffffu, pa[j][c01], msk);
#pragma unroll
                    for (int l = 0; l < 4; ++l)
                        pz[l][j][c01] +=
                            __shfl_xor_sync(0xffffffffu, pz[l][j][c01], msk);
                }
        }

        if (lane < 4) {  // lane == tig; all gid-groups hold identical sums
#pragma unroll
            for (int j = 0; j < 3; ++j)
#pragma unroll
                for (int c01 = 0; c01 < 2; ++c01) {
                    int nl = wn * 24 + j * 8 + 2 * lane + c01;
                    hbuf[wm4][0][nl] = pa[j][c01];
#pragma unroll
                    for (int l = 0; l < 4; ++l)
                        hbuf[wm4][1 + l][nl] = pz[l][j][c01];
                }
        }
        __syncthreads();

        for (int idx = tid; idx < 5 * 48; idx += 256) {
            int h = idx / 48, nl = idx - h * 48;
            float s = hbuf[0][h][nl] + hbuf[1][h][nl] + hbuf[2][h][nl]
                    + hbuf[3][h][nl];
            int ng = n0 + nl;
            if (h == 0)
                attn_out[(b * RCOUNT + rsub) * NHW + ng] = s + bap[0];
            else
                z_out[((b * 4 + (h - 1)) * RCOUNT + rsub) * NHW + ng] =
                    s + bzp[h - 1];
        }
        __syncthreads();   // hbuf reuse barrier for pass 1
    }
}

// ============================================================
// K4: scatter combine (betas) + p_r; writes attn, z, theta,
//     p_r, offsets directly into d_out
// ============================================================
__global__ void combine_kern(const float* __restrict__ rw,
                             const float* __restrict__ gr,
                             float* __restrict__ out) {
    int idx = blockIdx.x * blockDim.x + threadIdx.x;
    if (idx >= NB * NR * NHW) return;

    float l0 = (rw[0] + gr[0]) / 10.0f;
    float l1 = (rw[1] + gr[1]) / 10.0f;
    float mm = fmaxf(l0, l1);
    float e0 = expf(l0 - mm), e1 = expf(l1 - mm);
    float inv = 1.0f / (e0 + e1);
    float b0 = e0 * inv, b1 = e1 * inv;

    int b = idx / (NR * NHW);
    int rem = idx - b * (NR * NHW);
    int r = rem / NHW;
    int hw = rem - r * NHW;
    float off = c_offs[r];
    float t = off / PI_F;
    float pr = -0.5f * t * t - LOG_SIGMA - HALF_LOG2PI;

    float a = b1 * d_attn1[(b * NR + r) * NHW + hw];
    bool even = ((r & 1) == 0);
    if (even) a += b0 * d_attn0[(b * 4 + (r >> 1)) * NHW + hw];
    a += pr;
    out[OFF_ATTN + idx] = a;

    float zv[4];
#pragma unroll
    for (int l = 0; l < 4; ++l) {
        float z = b1 * d_z1[((b * 4 + l) * NR + r) * NHW + hw];
        if (even) z += b0 * d_z0[((b * 4 + l) * 4 + (r >> 1)) * NHW + hw];
        zv[l] = z;
        out[OFF_Z + ((b * 4 + l) * NR + r) * NHW + hw] = z;
    }
    out[OFF_TH + ((b * 2 + 0) * NR + r) * NHW + hw] = zv[0] + off;
    out[OFF_TH + ((b * 2 + 1) * NR + r) * NHW + hw] = zv[1];

    if (idx < 8) {
        float o2 = c_offs[idx];
        float t2 = o2 / PI_F;
        out[OFF_PR + idx] = -0.5f * t2 * t2 - LOG_SIGMA - HALF_LOG2PI;
        out[OFF_OFF + idx] = o2;
    }
}

// ============================================================
// K5: per-batch softmax stats (max / sumexp, two distributions)
// ============================================================
__global__ void stats_kern(const float* __restrict__ out,
                           const float* __restrict__ g) {
    __shared__ float sm[256];
    int b = blockIdx.x, tid = threadIdx.x;
    const float* a = out + OFF_ATTN + b * (NR * NHW);
    const float* gb = g + b * (NR * NHW);

    float m1 = -1e30f, m2 = -1e30f;
    for (int i = tid; i < NR * NHW; i += 256) {
        float v = a[i];
        m1 = fmaxf(m1, v);
        m2 = fmaxf(m2, v + gb[i]);
    }
    sm[tid] = m1; __syncthreads();
    for (int s = 128; s > 0; s >>= 1) {
        if (tid < s) sm[tid] = fmaxf(sm[tid], sm[tid + s]);
        __syncthreads();
    }
    m1 = sm[0]; __syncthreads();
    sm[tid] = m2; __syncthreads();
    for (int s = 128; s > 0; s >>= 1) {
        if (tid < s) sm[tid] = fmaxf(sm[tid], sm[tid + s]);
        __syncthreads();
    }
    m2 = sm[0]; __syncthreads();

    float s1 = 0.0f, s2 = 0.0f;
    for (int i = tid; i < NR * NHW; i += 256) {
        float v = a[i];
        s1 += expf(v - m1);
        s2 += expf(v + gb[i] - m2);
    }
    sm[tid] = s1; __syncthreads();
    for (int s = 128; s > 0; s >>= 1) {
        if (tid < s) sm[tid] += sm[tid + s];
        __syncthreads();
    }
    s1 = sm[0]; __syncthreads();
    sm[tid] = s2; __syncthreads();
    for (int s = 128; s > 0; s >>= 1) {
        if (tid < s) sm[tid] += sm[tid + s];
        __syncthreads();
    }
    s2 = sm[0];

    if (tid == 0) {
        d_stats[b * 4 + 0] = m1;
        d_stats[b * 4 + 1] = s1;
        d_stats[b * 4 + 2] = m2;
        d_stats[b * 4 + 3] = s2;
    }
}

// ============================================================
// K6: q_t_r (log_softmax) + a_sampled (gumbel softmax)
// ============================================================
__global__ void final_kern(const float* __restrict__ g,
                           float* __restrict__ out) {
    int idx = blockIdx.x * blockDim.x + threadIdx.x;
    if (idx >= NB * NR * NHW) return;
    int b = idx / (NR * NHW);
    float v = out[OFF_ATTN + idx];
    out[OFF_Q + idx] = (v - d_stats[b * 4 + 0]) - logf(d_stats[b * 4 + 1]);
    out[OFF_A + idx] =
        expf(v + g[idx] - d_stats[b * 4 + 2]) / d_stats[b * 4 + 3];
}

// ============================================================
extern "C" void kernel_launch(void* const* d_in, const int* in_sizes, int n_in,
                              void* d_out, int out_size) {
    const float* x   = (const float*)d_in[0];
    const float* ksw = (const float*)d_in[1];
    const float* rdw = (const float*)d_in[2];
    const float* w17 = (const float*)d_in[3];
    const float* b17 = (const float*)d_in[4];
    const float* w33 = (const float*)d_in[5];
    const float* b33 = (const float*)d_in[6];
    const float* w2  = (const float*)d_in[7];
    const float* b2  = (const float*)d_in[8];
    const float* wa  = (const float*)d_in[9];
    const float* ba  = (const float*)d_in[10];
    const float* wz  = (const float*)d_in[11];
    const float* bz  = (const float*)d_in[12];
    const float* gk  = (const float*)d_in[13];
    const float* gr  = (const float*)d_in[14];
    const float* ga  = (const float*)d_in[15];
    float* out = (float*)d_out;

    // word counts: K=17: 8*8*20*128 = 163840; K=33: 8*8*71*128 = 581632
    rotate_h<17, 9, 20><<<(163840 + 255) / 256, 256>>>(w17);
    rotate_h<33, 17, 71><<<(581632 + 255) / 256, 256>>>(w33);
    w2h_frag<<<(16384 + 255) / 256, 256>>>(w2);

    conv_fused<<<dim3(24, 128), 256>>>(x, b17, b33, ksw, gk);

    gemm_fused<<<dim3(48, 64), 256>>>(b2, wa, ba, wz, bz);

    combine_kern<<<(NB * NR * NHW + 255) / 256, 256>>>(rdw, gr, out);
    stats_kern<<<NB, 256>>>(out, ga);
    final_kern<<<(NB * NR * NHW + 255) / 256, 256>>>(ga, out);
}